// round 17
// baseline (speedup 1.0000x reference)
#include <cuda_runtime.h>
#include <cuda_bf16.h>
#include <mma.h>
#include <math.h>

using namespace nvcuda;

// Problem constants (from reference)
#define Bn    16
#define Tn    512
#define Dn    256
#define Vn    4233
#define LMAXn 64
#define Sn    129          // 2*LMAX+1 extended states
#define NLAB  65           // blank + LMAX distinct label slots per batch
#define BT    (Bn * Tn)    // 8192 rows
#define NCT   34           // ceil(Vn / 128) column tiles
#define NEGF  (-1e30f)
#define LOG2E_F 1.4426950408889634f
#define LN2_F   0.6931471805599453f

// ---- device scratch (allocation-free rule: static __device__ arrays) ----
__device__ float g_psum[NCT * BT];            // per-coltile partial sum(exp(logit))
__device__ float g_lse[BT];                   // log(sum(exp(logit))) per (b,t)
__device__ float g_lab[Bn * Tn * NLAB];       // raw logits at blank + labels (fp32)
__device__ float g_ll[Bn];                    // per-batch log-likelihood

__device__ __forceinline__ float ex2f(float x) {
    float r; asm("ex2.approx.ftz.f32 %0, %1;" : "=f"(r) : "f"(x)); return r;
}
__device__ __forceinline__ float lg2f(float x) {
    float r; asm("lg2.approx.ftz.f32 %0, %1;" : "=f"(r) : "f"(x)); return r;
}

// ============================================================
// Kernel A: label logits (raw fp32). Block = (b, 8 t's), one t per warp.
// Full fp32 precision for the 65 logits the DP actually consumes.
// ============================================================
__global__ __launch_bounds__(256) void ka_label_logits(
    const float* __restrict__ hs, const float* __restrict__ W,
    const float* __restrict__ bias, const int* __restrict__ ys_pad)
{
    __shared__ float hs_s[8][256];
    __shared__ float wsh[256];
    int b   = blockIdx.y;
    int t0  = blockIdx.x * 8;
    int tid = threadIdx.x;
    int w    = tid >> 5;
    int lane = tid & 31;

    const float4* hsg  = (const float4*)(hs + (size_t)(b * Tn + t0) * Dn);
    float4*       hss4 = (float4*)&hs_s[0][0];
    hss4[tid]       = hsg[tid];
    hss4[tid + 256] = hsg[tid + 256];

    float* outrow = g_lab + (size_t)(b * Tn + t0 + w) * NLAB;

    for (int li = 0; li < NLAB; li++) {
        int lab = (li == 0) ? 0 : ys_pad[b * LMAXn + li - 1];
        wsh[tid] = W[(size_t)lab * Dn + tid];
        __syncthreads();
        float partial = 0.f;
        #pragma unroll
        for (int i = 0; i < 8; i++)
            partial += hs_s[w][lane + 32 * i] * wsh[lane + 32 * i];
        #pragma unroll
        for (int d = 16; d >= 1; d >>= 1)
            partial += __shfl_xor_sync(0xffffffffu, partial, d);
        if (lane == 0) {
            outrow[li] = partial + bias[lab];
        }
        __syncthreads();
    }
}

// ============================================================
// Kernel B: bf16 tensor-core GEMM (wmma m16n16k16, fp32 accum) with
// fused sum(exp(logit+bias)) epilogue.
// Block tile 128x128, 8 warps as 4(M) x 2(N) -> warp tile 32x64.
// K in 8 slabs of 32, inline fp32->bf16 conversion into smem.
// Smem row stride 40 elems (80B = 20-bank step): ldmatrix conflict-free.
// ============================================================
#define LDSM 40
__global__ __launch_bounds__(256) void kb_gemm_sumexp(
    const float* __restrict__ hs, const float* __restrict__ W,
    const float* __restrict__ bias)
{
    __shared__ __align__(32) __nv_bfloat16 Asm[128][LDSM];
    __shared__ __align__(32) __nv_bfloat16 Bsm[128][LDSM];
    __shared__ float stg[8 * 256];     // per-warp 16x16 fp32 staging
    __shared__ float rowsum[128];
    __shared__ float bsh[128];

    int ct = blockIdx.x, rt = blockIdx.y;
    int r0 = rt * 128, c0 = ct * 128;
    int tid = threadIdx.x;
    int wid = tid >> 5, lane = tid & 31;
    int wm = wid & 3, wn = wid >> 2;    // 4 x 2 warp grid

    if (tid < 128) {
        rowsum[tid] = 0.f;
        int c = c0 + tid;
        bsh[tid] = (c < Vn) ? bias[c] : NEGF;   // exp(acc + NEGF) == 0
    }

    wmma::fragment<wmma::accumulator, 16, 16, 16, float> acc[2][4];
    #pragma unroll
    for (int mi = 0; mi < 2; mi++)
        #pragma unroll
        for (int ni = 0; ni < 4; ni++)
            wmma::fill_fragment(acc[mi][ni], 0.f);

    // gmem load mapping: 4 float4 per thread per tensor per slab
    // idx = tid + 256*i ; row = idx>>3 ; kc = (idx&7)*4
    #pragma unroll 1
    for (int ks = 0; ks < Dn; ks += 32) {
        __syncthreads();   // protect smem from previous slab's readers
        #pragma unroll
        for (int i = 0; i < 4; i++) {
            int idx = tid + 256 * i;
            int row = idx >> 3;
            int kc  = (idx & 7) << 2;
            // A: hs rows
            float4 va = *(const float4*)(hs + (size_t)(r0 + row) * Dn + ks + kc);
            __nv_bfloat162 a01 = __floats2bfloat162_rn(va.x, va.y);
            __nv_bfloat162 a23 = __floats2bfloat162_rn(va.z, va.w);
            *(__nv_bfloat162*)&Asm[row][kc]     = a01;
            *(__nv_bfloat162*)&Asm[row][kc + 2] = a23;
            // B: W rows (guard tail col tile)
            int cb = c0 + row;
            float4 vb = (cb < Vn) ? *(const float4*)(W + (size_t)cb * Dn + ks + kc)
                                  : make_float4(0.f, 0.f, 0.f, 0.f);
            __nv_bfloat162 b01 = __floats2bfloat162_rn(vb.x, vb.y);
            __nv_bfloat162 b23 = __floats2bfloat162_rn(vb.z, vb.w);
            *(__nv_bfloat162*)&Bsm[row][kc]     = b01;
            *(__nv_bfloat162*)&Bsm[row][kc + 2] = b23;
        }
        __syncthreads();

        #pragma unroll
        for (int kk = 0; kk < 32; kk += 16) {
            wmma::fragment<wmma::matrix_a, 16, 16, 16, __nv_bfloat16, wmma::row_major> af[2];
            wmma::fragment<wmma::matrix_b, 16, 16, 16, __nv_bfloat16, wmma::col_major> bf[4];
            #pragma unroll
            for (int mi = 0; mi < 2; mi++)
                wmma::load_matrix_sync(af[mi], &Asm[32 * wm + 16 * mi][kk], LDSM);
            #pragma unroll
            for (int ni = 0; ni < 4; ni++)
                wmma::load_matrix_sync(bf[ni], &Bsm[64 * wn + 16 * ni][kk], LDSM);
            #pragma unroll
            for (int mi = 0; mi < 2; mi++)
                #pragma unroll
                for (int ni = 0; ni < 4; ni++)
                    wmma::mma_sync(acc[mi][ni], af[mi], bf[ni], acc[mi][ni]);
        }
    }
    __syncthreads();   // mainloop done; rowsum zeroing also visible

    // epilogue: per warp, stage each 16x16 frag, exp+bias, row-sum
    float* mystg = stg + wid * 256;
    int row  = lane >> 1;          // 0..15 within frag
    int half = lane & 1;           // col half
    float racc[2] = {0.f, 0.f};
    #pragma unroll
    for (int mi = 0; mi < 2; mi++) {
        #pragma unroll
        for (int ni = 0; ni < 4; ni++) {
            wmma::store_matrix_sync(mystg, acc[mi][ni], 16, wmma::mem_row_major);
            __syncwarp();
            int bcol = 64 * wn + 16 * ni + 8 * half;
            float s8 = 0.f;
            #pragma unroll
            for (int c = 0; c < 8; c++)
                s8 += __expf(mystg[row * 16 + 8 * half + c] + bsh[bcol + c]);
            s8 += __shfl_xor_sync(0xffffffffu, s8, 1);
            if (half == 0) racc[mi] += s8;
            __syncwarp();
        }
    }
    if (half == 0) {
        atomicAdd(&rowsum[32 * wm + 0  + row], racc[0]);
        atomicAdd(&rowsum[32 * wm + 16 + row], racc[1]);
    }
    __syncthreads();
    if (tid < 128)
        g_psum[ct * BT + r0 + tid] = rowsum[tid];
}

// ============================================================
// Kernel C: combine partials -> log-sum-exp per row
// ============================================================
__global__ void kc_lse()
{
    int r = blockIdx.x * blockDim.x + threadIdx.x;
    if (r < BT) {
        float s = 0.f;
        #pragma unroll
        for (int ct = 0; ct < NCT; ct++) s += g_psum[ct * BT + r];
        g_lse[r] = logf(s);
    }
}

// ============================================================
// Kernel D: CTC forward DP in LOG2 domain. One warp per batch.
// Lane L owns states 4L..4L+3 (lane 31 also owns state 128).
// Only ONE cross-lane value needed per step: a3 of lane L-1.
// Gmem prefetch depth 2 (> L2 latency). No barriers, no LDS in loop.
// ============================================================
__global__ __launch_bounds__(32) void kd_ctc_dp(
    const int* __restrict__ hlens, const int* __restrict__ ys_pad,
    const int* __restrict__ ys_lens)
{
    const unsigned FULL = 0xffffffffu;
    __shared__ float fin[136];
    int b = blockIdx.x;
    int L = threadIdx.x;

    const float* lb   = g_lab + (size_t)b * Tn * NLAB;
    const float* lseb = g_lse + b * Tn;

    // allow flags for the two odd states this lane owns
    // s=4L+1 -> k=2L  : allowed iff s>=3 (L>=1) and ys[2L] != ys[2L-1]
    // s=4L+3 -> k=2L+1: allowed iff ys[2L+1] != ys[2L]
    const int* ys = ys_pad + b * LMAXn;
    bool allow1 = (L >= 1) && (ys[2 * L] != ys[2 * L - 1]);
    bool allow3 = (ys[2 * L + 1] != ys[2 * L]);

    float a0 = NEGF, a1 = NEGF, a2 = NEGF, a3 = NEGF, a4 = NEGF;
    {
        float lse0 = lseb[0];
        if (L == 0) {
            a0 = (lb[0] - lse0) * LOG2E_F;
            a1 = (lb[1] - lse0) * LOG2E_F;
        }
    }

    // prefetch pipeline depth 2: label indices for this lane: blank, 2L+1, 2L+2
    int i1 = 2 * L + 1, i2 = 2 * L + 2;
    float pb[2], p1[2], p2[2], pl[2];
    #pragma unroll
    for (int q = 0; q < 2; q++) {
        int t = 1 + q;
        pb[q] = lb[(size_t)t * NLAB];
        p1[q] = lb[(size_t)t * NLAB + i1];
        p2[q] = lb[(size_t)t * NLAB + i2];
        pl[q] = lseb[t];
    }

    int hl   = hlens[b];
    int tend = (hl < Tn) ? hl : Tn;   // alpha frozen for t >= hlen -> just stop

    for (int t = 1; t < tend; t++) {
        int sl = (t - 1) & 1;
        float lse  = pl[sl];
        float lpb  = (pb[sl] - lse) * LOG2E_F;
        float lp1  = (p1[sl] - lse) * LOG2E_F;
        float lp2v = (p2[sl] - lse) * LOG2E_F;
        if (t + 2 < Tn) {      // refill slot for t+2
            int tt = t + 2;
            pb[sl] = lb[(size_t)tt * NLAB];
            p1[sl] = lb[(size_t)tt * NLAB + i1];
            p2[sl] = lb[(size_t)tt * NLAB + i2];
            pl[sl] = lseb[tt];
        }

        float o3 = __shfl_up_sync(FULL, a3, 1);   // state 4L-1 from lane L-1
        if (L == 0) o3 = NEGF;

        // n0 (even s=4L):   LSE(a0, o3)
        float m0 = fmaxf(a0, o3);
        float n0 = m0 + lg2f(ex2f(a0 - m0) + ex2f(o3 - m0)) + lpb;
        // n1 (odd s=4L+1):  LSE(a1, a0, allow1 ? o3)
        float c1 = allow1 ? o3 : NEGF;
        float m1 = fmaxf(fmaxf(a1, a0), c1);
        float n1 = m1 + lg2f(ex2f(a1 - m1) + ex2f(a0 - m1) + ex2f(c1 - m1)) + lp1;
        // n2 (even s=4L+2): LSE(a2, a1)
        float m2 = fmaxf(a2, a1);
        float n2 = m2 + lg2f(ex2f(a2 - m2) + ex2f(a1 - m2)) + lpb;
        // n3 (odd s=4L+3):  LSE(a3, a2, allow3 ? a1)
        float c3 = allow3 ? a1 : NEGF;
        float m3 = fmaxf(fmaxf(a3, a2), c3);
        float n3 = m3 + lg2f(ex2f(a3 - m3) + ex2f(a2 - m3) + ex2f(c3 - m3)) + lp2v;
        // n4 (even s=128, lane 31 only — junk elsewhere, unused)
        float m4 = fmaxf(a4, a3);
        float n4 = m4 + lg2f(ex2f(a4 - m4) + ex2f(a3 - m4)) + lpb;

        a0 = n0; a1 = n1; a2 = n2; a3 = n3; a4 = n4;
    }

    // gather final alphas, combine last two states
    fin[4 * L + 0] = a0; fin[4 * L + 1] = a1;
    fin[4 * L + 2] = a2; fin[4 * L + 3] = a3;
    if (L == 31) fin[128] = a4;
    __syncwarp();
    if (L == 0) {
        int last = 2 * ys_lens[b];
        float vl = fin[last], vp = fin[last - 1];
        float m  = fmaxf(vl, vp);
        g_ll[b] = LN2_F * (m + lg2f(ex2f(vl - m) + ex2f(vp - m)));
    }
}

// ============================================================
// Kernel E: loss = -sum(ll)/B
// ============================================================
__global__ void ke_final(float* __restrict__ out)
{
    int lane = threadIdx.x;
    float v = (lane < Bn) ? g_ll[lane] : 0.f;
    #pragma unroll
    for (int d = 16; d >= 1; d >>= 1)
        v += __shfl_xor_sync(0xffffffffu, v, d);
    if (lane == 0) out[0] = -v / (float)Bn;
}

// ============================================================
extern "C" void kernel_launch(void* const* d_in, const int* in_sizes, int n_in,
                              void* d_out, int out_size)
{
    const float* hs      = (const float*)d_in[0];   // [B,T,D] f32
    const int*   hlens   = (const int*)d_in[1];     // [B] i32
    const int*   ys_pad  = (const int*)d_in[2];     // [B,LMAX] i32
    const int*   ys_lens = (const int*)d_in[3];     // [B] i32
    const float* W       = (const float*)d_in[4];   // [V,D] f32
    const float* bias    = (const float*)d_in[5];   // [V] f32
    float*       out     = (float*)d_out;           // scalar f32

    ka_label_logits<<<dim3(Tn / 8, Bn), 256>>>(hs, W, bias, ys_pad);
    kb_gemm_sumexp<<<dim3(NCT, BT / 128), 256>>>(hs, W, bias);
    kc_lse<<<32, 256>>>();
    kd_ctc_dp<<<Bn, 32>>>(hlens, ys_pad, ys_lens);
    ke_final<<<1, 32>>>(out);
}